// round 5
// baseline (speedup 1.0000x reference)
#include <cuda_runtime.h>
#include <cuda_bf16.h>
#include <cstdint>

// Problem constants (dataset-fixed)
#define HDIM   256
#define KOCC   8
#define KSUBJ  16
#define NBIN   128
#define CAP    2048
#define MT     128          // rows per CTA tile
#define NCOL   40           // logit cols = 5 mma n8-tiles exactly
#define NCTA_BIN 128        // binning CTAs (all co-resident on 148 SMs)

// smem layout (uint32 offsets into dynamic smem)
#define SA      20                       // A row stride (words); g*20 mod 32 distinct -> conflict-free
#define AW      (128 * SA)               // words per A buffer component (2560)
#define SB      132                      // B col stride (words)
#define A_H0    0
#define A_H1    AW
#define A_L0    (2 * AW)
#define A_L1    (3 * AW)
#define B_H     (4 * AW)                 // 10240
#define B_L     (B_H + NCOL * SB)        // + 5280
#define DSM_WORDS (B_L + NCOL * SB)      // 20800 words = 83200 B

__device__ int g_cursor[NBIN];
__device__ int g_sorted[NBIN * CAP];
__device__ int g_hist[NCTA_BIN * NBIN];
__device__ int g_sync;                   // monotonic epoch counter (never reset)

// ---------------------------------------------------------------------------
// Fused binning: histogram -> grid-sync -> prefix -> place.  One launch.
__global__ __launch_bounds__(256) void k_bin(const int* __restrict__ xp,
                                             const int* __restrict__ xo, int n) {
    __shared__ int hcnt[NBIN];
    __shared__ int sbase[NBIN];
    int t = threadIdx.x, c = blockIdx.x;
    if (t < NBIN) hcnt[t] = 0;
    __syncthreads();

    int base = c * 1024;
    int occ[4], pos[4];
#pragma unroll
    for (int j = 0; j < 4; j++) {
        int i = base + j * 256 + t;
        if (i < n) { occ[j] = xp[i] * KOCC + xo[i]; pos[j] = atomicAdd(&hcnt[occ[j]], 1); }
        else occ[j] = -1;
    }
    __syncthreads();

    if (t < NBIN) g_hist[c * NBIN + t] = hcnt[t];
    __threadfence();

    // grid-wide sync: every launch adds exactly NCTA_BIN; epoch = v / NCTA_BIN
    if (t == 0) {
        int v = atomicAdd(&g_sync, 1);
        int target = ((v >> 7) + 1) << 7;
        volatile int* gs = &g_sync;
        while (*gs < target) { }
    }
    __syncthreads();

    // per-bin prefix over CTA histograms; CTA 0 also writes totals
    if (t < NBIN) {
        int b = 0;
        for (int cc = 0; cc < c; cc++) b += g_hist[cc * NBIN + t];
        sbase[t] = b;
        if (c == 0) {
            int tot = 0;
            for (int cc = 0; cc < NCTA_BIN; cc++) tot += g_hist[cc * NBIN + t];
            g_cursor[t] = tot;
        }
    }
    __syncthreads();

#pragma unroll
    for (int j = 0; j < 4; j++)
        if (occ[j] >= 0) {
            int p = sbase[occ[j]] + pos[j];
            if (p < CAP) g_sorted[occ[j] * CAP + p] = base + j * 256 + t;
        }
}

// ---------------------------------------------------------------------------
// fp32 pair -> bf16x2 (hi) + bf16x2 (lo residual).  Lower 16 bits = first elem.
__device__ __forceinline__ void split2(float a, float b, uint32_t& hi, uint32_t& lo) {
    asm("cvt.rn.bf16x2.f32 %0, %1, %2;" : "=r"(hi) : "f"(b), "f"(a));
    float ha = __uint_as_float(hi << 16);
    float hb = __uint_as_float(hi & 0xffff0000u);
    float ra = a - ha, rb = b - hb;
    asm("cvt.rn.bf16x2.f32 %0, %1, %2;" : "=r"(lo) : "f"(rb), "f"(ra));
}

__device__ __forceinline__ void mma16816(float& d0, float& d1, float& d2, float& d3,
                                         uint32_t a0, uint32_t a1, uint32_t a2, uint32_t a3,
                                         uint32_t b0, uint32_t b1) {
    asm volatile(
        "mma.sync.aligned.m16n8k16.row.col.f32.bf16.bf16.f32 "
        "{%0,%1,%2,%3}, {%4,%5,%6,%7}, {%8,%9}, {%0,%1,%2,%3};"
        : "+f"(d0), "+f"(d1), "+f"(d2), "+f"(d3)
        : "r"(a0), "r"(a1), "r"(a2), "r"(a3), "r"(b0), "r"(b1));
}

// ---------------------------------------------------------------------------
__global__ __launch_bounds__(256, 2) void k_main(
    const float* __restrict__ X,
    const float* __restrict__ Wp, const float* __restrict__ bp,
    const float* __restrict__ Wo, const float* __restrict__ bo,
    const float* __restrict__ Ws, const float* __restrict__ bs2,
    const int* __restrict__ subj, float* __restrict__ out, int n)
{
    __shared__ int   rowidx[MT];
    __shared__ float biasz[NCOL];
    extern __shared__ uint32_t sm[];

    int bin  = blockIdx.x;
    int cnt  = g_cursor[bin];
    int base = blockIdx.y * MT;
    if (base >= cnt) return;
    int nrows = min(MT, cnt - base);
    int phase = bin >> 3, occl = bin & 7;
    int t = threadIdx.x, lane = t & 31, w = t >> 5;
    int g = lane >> 2, tig = lane & 3;

    if (t < MT)
        rowidx[t] = g_sorted[bin * CAP + base + ((t < nrows) ? t : 0)];
    if (t < NCOL)
        biasz[t] = (t < 16) ? bp[t]
                 : (t < 24) ? bo[phase * KOCC + (t - 16)]
                            : bs2[bin * KSUBJ + (t - 24)];
    __syncthreads();

    auto wrow = [&](int col) -> const float* {
        if (col < 16)      return Wp + col * HDIM;
        else if (col < 24) return Wo + (phase * KOCC + col - 16) * HDIM;
        else               return Ws + (bin * KSUBJ + col - 24) * HDIM;
    };

    // ---- stage full B panel (40 x 256) as bf16 hi/lo, stride SB ----------
#pragma unroll
    for (int j = 0; j < 10; j++) {
        int u   = t + j * 256;            // 0..2559 (float4 index)
        int col = u >> 6, f = u & 63;
        float4 wv = ((const float4*)wrow(col))[f];
        uint32_t h0, l0, h1, l1;
        split2(wv.x, wv.y, h0, l0);
        split2(wv.z, wv.w, h1, l1);
        *(uint2*)&sm[B_H + col * SB + f * 2] = make_uint2(h0, h1);
        *(uint2*)&sm[B_L + col * SB + f * 2] = make_uint2(l0, l1);
    }

    // ---- A pipeline: chunk = 32 k (16 kpairs), double-buffered ------------
    const int prow = t >> 1;                           // producer row
    const float4* xgp = (const float4*)(X + (size_t)rowidx[prow] * HDIM) + (t & 1) * 4;
    float4 pf[4];

    auto ldchunk = [&](int c) {
#pragma unroll
        for (int j = 0; j < 4; j++) pf[j] = xgp[c * 8 + j];
    };
    auto stage = [&](int b) {
        uint32_t hbase = (b ? A_H1 : A_H0) + prow * SA;
        uint32_t lbase = (b ? A_L1 : A_L0) + prow * SA;
        int f0 = (t & 1) * 4;
#pragma unroll
        for (int j = 0; j < 4; j++) {
            uint32_t h0, l0, h1, l1;
            split2(pf[j].x, pf[j].y, h0, l0);
            split2(pf[j].z, pf[j].w, h1, l1);
            int kp = (f0 + j) * 2;
            *(uint2*)&sm[hbase + kp] = make_uint2(h0, h1);
            *(uint2*)&sm[lbase + kp] = make_uint2(l0, l1);
        }
    };

    ldchunk(0);
    stage(0);
    ldchunk(1);
    __syncthreads();

    // ---- mma mainloop: warp w owns rows [16w,16w+16), all 5 n-tiles -------
    float acc[5][4];
#pragma unroll
    for (int nt = 0; nt < 5; nt++)
#pragma unroll
        for (int i = 0; i < 4; i++) acc[nt][i] = 0.f;

    const int r0 = w * 16;
    const uint32_t aoff0 = (r0 + g) * SA + tig;
    const uint32_t aoff1 = (r0 + g + 8) * SA + tig;

    for (int c = 0; c < 8; c++) {
        int b = c & 1;
        uint32_t hb = (b ? A_H1 : A_H0), lb = (b ? A_L1 : A_L0);
#pragma unroll
        for (int s = 0; s < 2; s++) {
            uint32_t o0 = s * 8 + aoff0, o1 = s * 8 + aoff1;
            uint32_t a0h = sm[hb + o0], a1h = sm[hb + o1];
            uint32_t a2h = sm[hb + o0 + 4], a3h = sm[hb + o1 + 4];
            uint32_t a0l = sm[lb + o0], a1l = sm[lb + o1];
            uint32_t a2l = sm[lb + o0 + 4], a3l = sm[lb + o1 + 4];
            int kpg = c * 16 + s * 8 + tig;
#pragma unroll
            for (int nt = 0; nt < 5; nt++) {
                uint32_t bo_ = (nt * 8 + g) * SB + kpg;
                uint32_t b0h = sm[B_H + bo_], b1h = sm[B_H + bo_ + 4];
                uint32_t b0l = sm[B_L + bo_], b1l = sm[B_L + bo_ + 4];
                mma16816(acc[nt][0], acc[nt][1], acc[nt][2], acc[nt][3],
                         a0h, a1h, a2h, a3h, b0h, b1h);
                mma16816(acc[nt][0], acc[nt][1], acc[nt][2], acc[nt][3],
                         a0h, a1h, a2h, a3h, b0l, b1l);
                mma16816(acc[nt][0], acc[nt][1], acc[nt][2], acc[nt][3],
                         a0l, a1l, a2l, a3l, b0h, b1h);
            }
        }
        if (c < 7) {
            stage(1 - b);                 // store prefetched chunk c+1
            if (c < 6) ldchunk(c + 2);    // gmem loads for chunk c+2
        }
        __syncthreads();
    }

    // ---- epilogue: D -> smem logits [128][41], per-row softmax ------------
    float* lg = (float*)sm;               // aliases dead A buffers (5248 <= 10240 words)
#pragma unroll
    for (int nt = 0; nt < 5; nt++) {
        int col = nt * 8 + 2 * tig;
        lg[(r0 + g) * 41 + col]         = acc[nt][0];
        lg[(r0 + g) * 41 + col + 1]     = acc[nt][1];
        lg[(r0 + g + 8) * 41 + col]     = acc[nt][2];
        lg[(r0 + g + 8) * 41 + col + 1] = acc[nt][3];
    }
    __syncthreads();

    if (t < nrows) {
        const float* Lr = lg + t * 41;
        int orig = rowidx[t];
        float L[NCOL];
#pragma unroll
        for (int j = 0; j < NCOL; j++) L[j] = Lr[j] + biasz[j];

        float m1 = L[0];
#pragma unroll
        for (int j = 1; j < 16; j++) m1 = fmaxf(m1, L[j]);
        float s1 = 0.f;
#pragma unroll
        for (int j = 0; j < 16; j++) s1 += expf(L[j] - m1);
        float p1 = expf(L[phase] - m1) / s1;

        float m2 = L[16];
#pragma unroll
        for (int j = 17; j < 24; j++) m2 = fmaxf(m2, L[j]);
        float s2 = 0.f;
#pragma unroll
        for (int j = 16; j < 24; j++) s2 += expf(L[j] - m2);
        float p2 = expf(L[16 + occl] - m2) / s2;

        int sj = subj[orig];
        float m3 = L[24];
#pragma unroll
        for (int j = 25; j < 40; j++) m3 = fmaxf(m3, L[j]);
        float s3 = 0.f;
#pragma unroll
        for (int j = 24; j < 40; j++) s3 += expf(L[j] - m3);
        float p3 = expf(L[24 + sj] - m3) / s3;

        float po = p1 * p2;
        out[orig]         = p1;
        out[n + orig]     = po;
        out[2 * n + orig] = po * p3;
    }
}

// ---------------------------------------------------------------------------
extern "C" void kernel_launch(void* const* d_in, const int* in_sizes, int n_in,
                              void* d_out, int out_size) {
    const float* X  = (const float*)d_in[0];
    const float* Wp = (const float*)d_in[1];
    const float* bp = (const float*)d_in[2];
    const float* Wo = (const float*)d_in[3];
    const float* bo = (const float*)d_in[4];
    const float* Ws = (const float*)d_in[5];
    const float* bs = (const float*)d_in[6];
    const int*   xp = (const int*)d_in[7];
    const int*   xo = (const int*)d_in[8];
    const int*   xs = (const int*)d_in[9];
    int n = in_sizes[0] / HDIM;
    float* out = (float*)d_out;

    static int cfg = 0;
    if (!cfg) {
        cudaFuncSetAttribute(k_main, cudaFuncAttributeMaxDynamicSharedMemorySize,
                             DSM_WORDS * 4);
        cfg = 1;
    }

    k_bin<<<NCTA_BIN, 256>>>(xp, xo, n);
    dim3 grid(NBIN, CAP / MT);
    k_main<<<grid, 256, DSM_WORDS * 4>>>(X, Wp, bp, Wo, bo, Ws, bs, xs, out, n);
}

// round 6
// speedup vs baseline: 1.4202x; 1.4202x over previous
#include <cuda_runtime.h>
#include <cuda_bf16.h>
#include <cstdint>

// Problem constants (dataset-fixed)
#define HDIM   256
#define KOCC   8
#define KSUBJ  16
#define NBIN   128
#define CAP    2048
#define MT     128          // rows per CTA tile
#define NCOL   40           // logit cols = 5 mma n8-tiles exactly
#define NCTA_MAIN (NBIN * (CAP / MT))   // 2048, fixed

// smem: B panel only. col stride 132 words -> (col*132+tig) banks all distinct.
#define SB      132
#define B_H     0
#define B_L     (NCOL * SB)              // 5280
#define DSM_WORDS (2 * NCOL * SB)        // 10560 words = 42.24 KB (< 48KB default)

__device__ int g_cursor2[2][NBIN];       // parity double-buffered (zero-init)
__device__ int g_sorted[NBIN * CAP];
__device__ int g_epoch;                  // bumped once per k_main completion
__device__ int g_done;                   // monotone CTA-completion counter

// ---------------------------------------------------------------------------
__global__ __launch_bounds__(256) void k_scatter(const int* __restrict__ xp,
                                                 const int* __restrict__ xo, int n) {
    __shared__ int hcnt[NBIN];
    __shared__ int hbase[NBIN];
    int p = (*(volatile int*)&g_epoch) & 1;
    int t = threadIdx.x;
    if (t < NBIN) hcnt[t] = 0;
    __syncthreads();
    int base = blockIdx.x * 1024;
    int occ[4], pos[4];
#pragma unroll
    for (int j = 0; j < 4; j++) {
        int i = base + j * 256 + t;
        if (i < n) { occ[j] = xp[i] * KOCC + xo[i]; pos[j] = atomicAdd(&hcnt[occ[j]], 1); }
        else occ[j] = -1;
    }
    __syncthreads();
    if (t < NBIN && hcnt[t] > 0) hbase[t] = atomicAdd(&g_cursor2[p][t], hcnt[t]);
    __syncthreads();
#pragma unroll
    for (int j = 0; j < 4; j++)
        if (occ[j] >= 0) {
            int q = hbase[occ[j]] + pos[j];
            if (q < CAP) g_sorted[occ[j] * CAP + q] = base + j * 256 + t;
        }
}

// ---------------------------------------------------------------------------
// fp32 pair -> bf16x2 (hi) + bf16x2 (lo residual).  Lower 16 bits = first elem.
__device__ __forceinline__ void split2(float a, float b, uint32_t& hi, uint32_t& lo) {
    asm("cvt.rn.bf16x2.f32 %0, %1, %2;" : "=r"(hi) : "f"(b), "f"(a));
    float ha = __uint_as_float(hi << 16);
    float hb = __uint_as_float(hi & 0xffff0000u);
    float ra = a - ha, rb = b - hb;
    asm("cvt.rn.bf16x2.f32 %0, %1, %2;" : "=r"(lo) : "f"(rb), "f"(ra));
}

__device__ __forceinline__ void mma16816(float& d0, float& d1, float& d2, float& d3,
                                         uint32_t a0, uint32_t a1, uint32_t a2, uint32_t a3,
                                         uint32_t b0, uint32_t b1) {
    asm volatile(
        "mma.sync.aligned.m16n8k16.row.col.f32.bf16.bf16.f32 "
        "{%0,%1,%2,%3}, {%4,%5,%6,%7}, {%8,%9}, {%0,%1,%2,%3};"
        : "+f"(d0), "+f"(d1), "+f"(d2), "+f"(d3)
        : "r"(a0), "r"(a1), "r"(a2), "r"(a3), "r"(b0), "r"(b1));
}

__device__ __forceinline__ void cta_done() {
    int v = atomicAdd(&g_done, 1);
    if ((v & (NCTA_MAIN - 1)) == NCTA_MAIN - 1) atomicAdd(&g_epoch, 1);
}

// ---------------------------------------------------------------------------
__global__ __launch_bounds__(256, 3) void k_main(
    const float* __restrict__ X,
    const float* __restrict__ Wp, const float* __restrict__ bp,
    const float* __restrict__ Wo, const float* __restrict__ bo,
    const float* __restrict__ Ws, const float* __restrict__ bs2,
    const int* __restrict__ subj, float* __restrict__ out, int n)
{
    __shared__ int   rowidx[MT];
    __shared__ float biasz[NCOL];
    extern __shared__ uint32_t sm[];

    int p = (*(volatile int*)&g_epoch) & 1;
    int bin  = blockIdx.x;
    int t = threadIdx.x;

    // zero the OTHER parity's cursors for the next replay (safe: next scatter
    // launches only after this kernel fully completes)
    if (bin == 0 && blockIdx.y == 0 && t < NBIN) g_cursor2[1 - p][t] = 0;

    int cnt  = g_cursor2[p][bin];
    int base = blockIdx.y * MT;
    if (base >= cnt) { if (t == 0) cta_done(); return; }
    int nrows = min(MT, cnt - base);
    int phase = bin >> 3, occl = bin & 7;
    int lane = t & 31, w = t >> 5;
    int g = lane >> 2, tig = lane & 3;

    if (t < MT)
        rowidx[t] = g_sorted[bin * CAP + base + ((t < nrows) ? t : 0)];
    if (t < NCOL)
        biasz[t] = (t < 16) ? bp[t]
                 : (t < 24) ? bo[phase * KOCC + (t - 16)]
                            : bs2[bin * KSUBJ + (t - 24)];

    auto wrow = [&](int col) -> const float* {
        if (col < 16)      return Wp + col * HDIM;
        else if (col < 24) return Wo + (phase * KOCC + col - 16) * HDIM;
        else               return Ws + (bin * KSUBJ + col - 24) * HDIM;
    };

    // ---- stage B panel (40 x 256) as bf16 hi/lo ---------------------------
#pragma unroll
    for (int j = 0; j < 10; j++) {
        int u   = t + j * 256;            // float4 index 0..2559
        int col = u >> 6, f = u & 63;
        float4 wv = ((const float4*)wrow(col))[f];
        uint32_t h0, l0, h1, l1;
        split2(wv.x, wv.y, h0, l0);
        split2(wv.z, wv.w, h1, l1);
        *(uint2*)&sm[B_H + col * SB + f * 2] = make_uint2(h0, h1);
        *(uint2*)&sm[B_L + col * SB + f * 2] = make_uint2(l0, l1);
    }
    __syncthreads();

    // ---- mainloop: A fragments straight from gmem, barrier-free -----------
    const int r0 = w * 16;
    const float2* xr0 = (const float2*)(X + (size_t)rowidx[r0 + g] * HDIM);
    const float2* xr1 = (const float2*)(X + (size_t)rowidx[r0 + g + 8] * HDIM);

    float2 buf[3][4];                     // chunk c, c+1, c+2 in flight
#pragma unroll
    for (int c0 = 0; c0 < 2; c0++) {
        buf[c0][0] = xr0[c0 * 8 + tig]; buf[c0][1] = xr0[c0 * 8 + tig + 4];
        buf[c0][2] = xr1[c0 * 8 + tig]; buf[c0][3] = xr1[c0 * 8 + tig + 4];
    }

    float acc[5][4];
#pragma unroll
    for (int nt = 0; nt < 5; nt++)
#pragma unroll
        for (int i = 0; i < 4; i++) acc[nt][i] = 0.f;

#pragma unroll
    for (int c = 0; c < 16; c++) {        // chunk = k16 = one mma k-step
        float2* cur = buf[c % 3];
        if (c < 14) {
            float2* nx = buf[(c + 2) % 3];
            nx[0] = xr0[(c + 2) * 8 + tig]; nx[1] = xr0[(c + 2) * 8 + tig + 4];
            nx[2] = xr1[(c + 2) * 8 + tig]; nx[3] = xr1[(c + 2) * 8 + tig + 4];
        }
        uint32_t a0h, a0l, a1h, a1l, a2h, a2l, a3h, a3l;
        split2(cur[0].x, cur[0].y, a0h, a0l);
        split2(cur[1].x, cur[1].y, a2h, a2l);
        split2(cur[2].x, cur[2].y, a1h, a1l);
        split2(cur[3].x, cur[3].y, a3h, a3l);
        int kpg = c * 8 + tig;
#pragma unroll
        for (int nt = 0; nt < 5; nt++) {
            uint32_t bo_ = (nt * 8 + g) * SB + kpg;
            uint32_t b0h = sm[B_H + bo_], b1h = sm[B_H + bo_ + 4];
            uint32_t b0l = sm[B_L + bo_], b1l = sm[B_L + bo_ + 4];
            mma16816(acc[nt][0], acc[nt][1], acc[nt][2], acc[nt][3],
                     a0h, a1h, a2h, a3h, b0h, b1h);
            mma16816(acc[nt][0], acc[nt][1], acc[nt][2], acc[nt][3],
                     a0h, a1h, a2h, a3h, b0l, b1l);
            mma16816(acc[nt][0], acc[nt][1], acc[nt][2], acc[nt][3],
                     a0l, a1l, a2l, a3l, b0h, b1h);
        }
    }

    // ---- epilogue: D -> smem logits [128][41] (aliases B), softmax --------
    __syncthreads();
    float* lg = (float*)sm;               // 5248 words <= 10560
#pragma unroll
    for (int nt = 0; nt < 5; nt++) {
        int col = nt * 8 + 2 * tig;
        lg[(r0 + g) * 41 + col]         = acc[nt][0];
        lg[(r0 + g) * 41 + col + 1]     = acc[nt][1];
        lg[(r0 + g + 8) * 41 + col]     = acc[nt][2];
        lg[(r0 + g + 8) * 41 + col + 1] = acc[nt][3];
    }
    __syncthreads();

    if (t < nrows) {
        const float* Lr = lg + t * 41;
        int orig = rowidx[t];
        float L[NCOL];
#pragma unroll
        for (int j = 0; j < NCOL; j++) L[j] = Lr[j] + biasz[j];

        float m1 = L[0];
#pragma unroll
        for (int j = 1; j < 16; j++) m1 = fmaxf(m1, L[j]);
        float s1 = 0.f;
#pragma unroll
        for (int j = 0; j < 16; j++) s1 += expf(L[j] - m1);
        float p1 = expf(L[phase] - m1) / s1;

        float m2 = L[16];
#pragma unroll
        for (int j = 17; j < 24; j++) m2 = fmaxf(m2, L[j]);
        float s2 = 0.f;
#pragma unroll
        for (int j = 16; j < 24; j++) s2 += expf(L[j] - m2);
        float p2 = expf(L[16 + occl] - m2) / s2;

        int sj = subj[orig];
        float m3 = L[24];
#pragma unroll
        for (int j = 25; j < 40; j++) m3 = fmaxf(m3, L[j]);
        float s3 = 0.f;
#pragma unroll
        for (int j = 24; j < 40; j++) s3 += expf(L[j] - m3);
        float p3 = expf(L[24 + sj] - m3) / s3;

        float po = p1 * p2;
        out[orig]         = p1;
        out[n + orig]     = po;
        out[2 * n + orig] = po * p3;
    }

    __syncthreads();
    if (t == 0) cta_done();
}

// ---------------------------------------------------------------------------
extern "C" void kernel_launch(void* const* d_in, const int* in_sizes, int n_in,
                              void* d_out, int out_size) {
    const float* X  = (const float*)d_in[0];
    const float* Wp = (const float*)d_in[1];
    const float* bp = (const float*)d_in[2];
    const float* Wo = (const float*)d_in[3];
    const float* bo = (const float*)d_in[4];
    const float* Ws = (const float*)d_in[5];
    const float* bs = (const float*)d_in[6];
    const int*   xp = (const int*)d_in[7];
    const int*   xo = (const int*)d_in[8];
    const int*   xs = (const int*)d_in[9];
    int n = in_sizes[0] / HDIM;
    float* out = (float*)d_out;

    k_scatter<<<(n + 1023) / 1024, 256>>>(xp, xo, n);
    dim3 grid(NBIN, CAP / MT);
    k_main<<<grid, 256, DSM_WORDS * 4>>>(X, Wp, bp, Wo, bo, Ws, bs, xs, out, n);
}